// round 17
// baseline (speedup 1.0000x reference)
#include <cuda_runtime.h>
#include <cuda_bf16.h>

// Shapes: query (N,T,C,L)=(32,64,256,64) fp32; key (T,N,C); out (T,N,C)
#define N_ 32
#define T_ 64
#define C_ 256
#define L_ 64
#define TG 16                        // t-groups per n (4 t's folded per block)
#define P_THRESH 1e-7f

__device__ float g_part[N_ * TG * L_];   // per-(n,tg) partial scores (128KB)

// ---------------------------------------------------------------------------
// Kernel 1: partial scores, 4 t-tiles folded per block (t reduces into
// scores too!). Grid 512 = (n, tg). Same proven inner loop; one cross-warp
// reduction per 4 tiles instead of per tile. Streams q front-to-back.
// ---------------------------------------------------------------------------
__global__ __launch_bounds__(256, 6) void k_scores(const float* __restrict__ q,
                                                   const float* __restrict__ key) {
    const int bid = blockIdx.x;        // 0..511
    const int n = bid >> 4;
    const int tg = bid & 15;
    const int w = threadIdx.x >> 5;
    const int lane = threadIdx.x & 31;
    const int half = lane >> 4;
    const int l4 = lane & 15;

    const float4* __restrict__ qb = reinterpret_cast<const float4*>(q);

    float4 acc = make_float4(0.f, 0.f, 0.f, 0.f);
    #pragma unroll
    for (int tt = 0; tt < 4; ++tt) {
        const int t = (tg << 2) + tt;
        // this warp's 32 key values for tile (n,t), one per lane
        const float kreg = key[((size_t)t * N_ + n) * C_ + (w << 5) + lane];
        const size_t rowbase = ((size_t)n * T_ + t) * C_;
        #pragma unroll
        for (int i = 0; i < 16; ++i) {
            const int r = (i << 1) + half;
            const float kv = __shfl_sync(0xffffffffu, kreg, r);
            const float4 qv = qb[(rowbase + (w << 5) + r) * 16 + l4];
            acc.x = fmaf(kv, qv.x, acc.x);
            acc.y = fmaf(kv, qv.y, acc.y);
            acc.z = fmaf(kv, qv.z, acc.z);
            acc.w = fmaf(kv, qv.w, acc.w);
        }
    }
    acc.x += __shfl_xor_sync(0xffffffffu, acc.x, 16);
    acc.y += __shfl_xor_sync(0xffffffffu, acc.y, 16);
    acc.z += __shfl_xor_sync(0xffffffffu, acc.z, 16);
    acc.w += __shfl_xor_sync(0xffffffffu, acc.w, 16);

    __shared__ float4 sm[8][16];
    if (half == 0) sm[w][l4] = acc;
    __syncthreads();
    if (threadIdx.x < 16) {
        float4 tot = sm[0][threadIdx.x];
        #pragma unroll
        for (int j = 1; j < 8; ++j) {
            const float4 v = sm[j][threadIdx.x];
            tot.x += v.x; tot.y += v.y; tot.z += v.z; tot.w += v.w;
        }
        reinterpret_cast<float4*>(g_part + (size_t)(n * TG + tg) * L_)[threadIdx.x] = tot;
    }
}

// ---------------------------------------------------------------------------
// Kernel 2 (fused, REVERSED): per-(n,t) block recomputes its n's softmax
// from the now-tiny g_part (4KB/block, L2-hot), compacts significant
// weights, then does the sparse gather against the L2-resident tail of q.
// ---------------------------------------------------------------------------
__global__ __launch_bounds__(256) void k_sg(const float* __restrict__ q,
                                            float* __restrict__ out) {
    const int b = (N_ * T_ - 1) - blockIdx.x;   // reversed for L2 reuse
    const int n = b >> 6;
    const int t = b & 63;
    const int tid = threadIdx.x;
    const int lane = tid & 31;

    __shared__ float s_part[4][L_];
    __shared__ float s_w[L_];
    __shared__ int   s_idx[L_];
    __shared__ int   s_cnt;
    __shared__ float s_red[4];

    // ---- phase 1: sum the 16 tg-partials; 4-way split, coalesced over l ----
    {
        const int l = tid & 63;
        const int qr = tid >> 6;               // quarter: 4 tg's each
        const float* __restrict__ p =
            g_part + (size_t)(n * TG + qr * 4) * L_ + l;
        float s = 0.f;
        #pragma unroll
        for (int j = 0; j < 4; ++j) s += p[j * L_];
        s_part[qr][l] = s;
    }
    __syncthreads();

    // ---- phase 2: softmax + compaction (threads 0..63) ----
    if (tid < L_) {
        const int w2 = tid >> 5;
        float s = s_part[0][tid] + s_part[1][tid]
                + s_part[2][tid] + s_part[3][tid];

        float m = s;
        #pragma unroll
        for (int off = 16; off; off >>= 1)
            m = fmaxf(m, __shfl_xor_sync(0xffffffffu, m, off));
        if (lane == 0) s_red[w2] = m;
        __syncwarp();
        __syncthreads();
        m = fmaxf(s_red[0], s_red[1]);

        const float e = __expf(s - m);
        float sum = e;
        #pragma unroll
        for (int off = 16; off; off >>= 1)
            sum += __shfl_xor_sync(0xffffffffu, sum, off);
        if (lane == 0) s_red[2 + w2] = sum;
        __syncthreads();
        const float prob = e / (s_red[2] + s_red[3]);

        const bool keep = prob > P_THRESH;
        const unsigned mask = __ballot_sync(0xffffffffu, keep);
        const int prefix = __popc(mask & ((1u << lane) - 1u));
        __shared__ int wcnt[2];
        if (lane == 0) wcnt[w2] = __popc(mask);
        __syncthreads();
        const int base = (w2 == 1) ? wcnt[0] : 0;
        if (keep) {
            s_w[base + prefix] = prob;
            s_idx[base + prefix] = tid;
        }
        if (tid == 0) s_cnt = wcnt[0] + wcnt[1];
    } else {
        __syncthreads();   // match phase-2 barriers
        __syncthreads();
        __syncthreads();
    }
    __syncthreads();

    // ---- phase 3: sparse gather (thread tid == c) ----
    const int cnt = s_cnt;
    const float* __restrict__ qrow = q + ((size_t)b * C_ + tid) * L_;
    float acc = 0.f;
    for (int j = 0; j < cnt; ++j)
        acc = fmaf(s_w[j], __ldg(qrow + s_idx[j]), acc);

    out[((size_t)t * N_ + n) * C_ + tid] = acc;
}

extern "C" void kernel_launch(void* const* d_in, const int* in_sizes, int n_in,
                              void* d_out, int out_size) {
    const float* q   = (const float*)d_in[0];
    const float* key = (const float*)d_in[1];
    float* out = (float*)d_out;

    k_scores<<<N_ * TG, 256>>>(q, key);
    k_sg<<<N_ * T_, 256>>>(q, out);
}